// round 1
// baseline (speedup 1.0000x reference)
#include <cuda_runtime.h>
#include <cstdint>

typedef unsigned long long ull;

#define M_TOTAL (4 * 256 * 256)

// Scratch for conv outputs (static __device__ arrays: allocation-guard safe)
__device__ float g_cm[(size_t)M_TOTAL * 64];
__device__ float g_cr[(size_t)M_TOTAL * 64];

// ---------------- packed f32x2 helpers ----------------
__device__ __forceinline__ ull fma2(ull a, ull b, ull c) {
    ull d;
    asm("fma.rn.f32x2 %0, %1, %2, %3;" : "=l"(d) : "l"(a), "l"(b), "l"(c));
    return d;
}
__device__ __forceinline__ ull add2(ull a, ull b) {
    ull d;
    asm("add.rn.f32x2 %0, %1, %2;" : "=l"(d) : "l"(a), "l"(b));
    return d;
}
__device__ __forceinline__ ull pack2(float x, float y) {
    ull r;
    asm("mov.b64 %0, {%1, %2};" : "=l"(r) : "f"(x), "f"(y));
    return r;
}
__device__ __forceinline__ float2 unpack2(ull v) {
    float2 r;
    asm("mov.b64 {%0, %1}, %2;" : "=f"(r.x), "=f"(r.y) : "l"(v));
    return r;
}

// ---------------- conv kernel: C = A[M,64] * W[64,64] ----------------
// BM=128 pixels per block, 128 threads, thread tile 8 pixels x 8 outputs.
// blockIdx.y = 0 -> main*Wm -> g_cm ; 1 -> ref*Wr -> g_cr
__global__ void __launch_bounds__(128) conv_kernel(
    const float* __restrict__ main_in, const float* __restrict__ ref_in,
    const float* __restrict__ Wm, const float* __restrict__ Wr)
{
    __shared__ float As[128 * 64];   // [m][c], column XOR-swizzled by (m>>3)&3
    __shared__ float Ws[64 * 64];    // [k][d]

    const float* A = blockIdx.y ? ref_in : main_in;
    const float* W = blockIdx.y ? Wr : Wm;
    float* outp   = blockIdx.y ? g_cr : g_cm;

    int t = threadIdx.x;
    size_t bM = (size_t)blockIdx.x * 128;

    // Load A tile (coalesced float4), store with XOR swizzle on channel index
    const float4* Ag = (const float4*)(A + bM * 64);
#pragma unroll
    for (int i = 0; i < 16; i++) {
        int idx = i * 128 + t;        // float4 index within tile
        float4 v = Ag[idx];
        int ml = idx >> 4;            // local pixel
        int c0 = (idx & 15) * 4;      // channel base
        int s = ml & 24;              // swizzle bits
        As[ml * 64 + ((c0 + 0) ^ s)] = v.x;
        As[ml * 64 + ((c0 + 1) ^ s)] = v.y;
        As[ml * 64 + ((c0 + 2) ^ s)] = v.z;
        As[ml * 64 + ((c0 + 3) ^ s)] = v.w;
    }
    // Load W (4096 floats)
    const float4* Wg4 = (const float4*)W;
    float4* Ws4 = (float4*)Ws;
#pragma unroll
    for (int i = 0; i < 8; i++)
        Ws4[i * 128 + t] = Wg4[i * 128 + t];

    __syncthreads();

    int tn = t & 7;    // output-column group: d = tn*4 .. +3  and  tn*4+32 .. +35
    int tm = t >> 3;   // pixel group: m = tm*8 .. +7
    int sw = (tm & 3) << 3;

    ull acc[8][4];
#pragma unroll
    for (int p = 0; p < 8; p++)
#pragma unroll
        for (int j = 0; j < 4; j++) acc[p][j] = 0ull;

    const float* arow = &As[(tm * 8) * 64];

#pragma unroll 8
    for (int k = 0; k < 64; k++) {
        int sk = k ^ sw;
        // Two conflict-free LDS.128: columns tn*4 and tn*4+32
        ulonglong2 w01 = *(const ulonglong2*)&Ws[k * 64 + tn * 4];
        ulonglong2 w23 = *(const ulonglong2*)&Ws[k * 64 + 32 + tn * 4];
        ull av[8];
#pragma unroll
        for (int p = 0; p < 8; p++) {
            float a = arow[p * 64 + sk];   // 4 distinct banks, broadcast x8
            av[p] = pack2(a, a);
        }
#pragma unroll
        for (int p = 0; p < 8; p++) {
            acc[p][0] = fma2(av[p], w01.x, acc[p][0]);
            acc[p][1] = fma2(av[p], w01.y, acc[p][1]);
            acc[p][2] = fma2(av[p], w23.x, acc[p][2]);
            acc[p][3] = fma2(av[p], w23.y, acc[p][3]);
        }
    }

    float* og = outp + bM * 64;
#pragma unroll
    for (int p = 0; p < 8; p++) {
        int m = tm * 8 + p;
        float2 x0 = unpack2(acc[p][0]), x1 = unpack2(acc[p][1]);
        float2 x2 = unpack2(acc[p][2]), x3 = unpack2(acc[p][3]);
        *(float4*)&og[m * 64 + tn * 4]      = make_float4(x0.x, x0.y, x1.x, x1.y);
        *(float4*)&og[m * 64 + 32 + tn * 4] = make_float4(x2.x, x2.y, x3.x, x3.y);
    }
}

// ---------------- attention kernel ----------------
// 16x16 pixel tile per block (256 threads, 1 thread = 1 pixel).
// conv_ref halo (20x20) staged in smem as [c2 plane][y][x] float2, stride 405 (odd).
#define CRS_STRIDE 405

__global__ void __launch_bounds__(256, 2) attn_kernel(
    const float* __restrict__ Wg, float* __restrict__ out)
{
    extern __shared__ ull smem[];
    ull* crs   = smem;                               // 32 * 405 ull = 103,680 B
    float* Wgs = (float*)(smem + 32 * CRS_STRIDE);   // 1600 floats = 6,400 B

    int t = threadIdx.x;
    int bx = blockIdx.x, by = blockIdx.y, b = blockIdx.z;

    // Stage Wg
    for (int i = t; i < 1600; i += 256) Wgs[i] = Wg[i];

    // This thread's pixel; issue conv_main loads early (MLP)
    int lx = t & 15, ly = t >> 4;
    int gy = by * 16 + ly, gx = bx * 16 + lx;
    size_t m = ((size_t)b * 256 + gy) * 256 + gx;

    ull cmv[32];
    {
        const ulonglong2* cp = (const ulonglong2*)(g_cm + m * 64);
#pragma unroll
        for (int i = 0; i < 16; i++) {
            ulonglong2 u = cp[i];
            cmv[2 * i] = u.x; cmv[2 * i + 1] = u.y;
        }
    }

    // Halo fill: one warp per halo pixel, lane = channel-pair (coalesced LDG.64).
    // OOB pixels -> 0, which reproduces the reference's zero padding (logit == 0).
    {
        int w = t >> 5, l = t & 31;
        for (int hp = w; hp < 400; hp += 8) {
            int hy = hp / 20, hx = hp - hy * 20;
            int y = by * 16 + hy - 2, x = bx * 16 + hx - 2;
            ull v = 0ull;
            if (y >= 0 && y < 256 && x >= 0 && x < 256) {
                size_t pm = ((size_t)b * 256 + y) * 256 + x;
                v = ((const ull*)g_cr)[pm * 32 + l];
            }
            crs[(size_t)l * CRS_STRIDE + hy * 20 + hx] = v;
        }
    }
    __syncthreads();

    // 25 logits: dot(conv_main, conv_ref[neighbor]) with 4-way accumulator ILP
    float logit[25];
    int base_off = ly * 20 + lx;
#pragma unroll
    for (int kk = 0; kk < 25; kk++) {
        int off = base_off + (kk / 5) * 20 + (kk % 5);
        const ull* cr0 = crs + off;
        ull a0 = 0, a1 = 0, a2 = 0, a3 = 0;
#pragma unroll
        for (int c2 = 0; c2 < 32; c2 += 4) {
            a0 = fma2(cmv[c2 + 0], cr0[(c2 + 0) * CRS_STRIDE], a0);
            a1 = fma2(cmv[c2 + 1], cr0[(c2 + 1) * CRS_STRIDE], a1);
            a2 = fma2(cmv[c2 + 2], cr0[(c2 + 2) * CRS_STRIDE], a2);
            a3 = fma2(cmv[c2 + 3], cr0[(c2 + 3) * CRS_STRIDE], a3);
        }
        a0 = add2(a0, a1); a2 = add2(a2, a3); a0 = add2(a0, a2);
        float2 s = unpack2(a0);
        logit[kk] = s.x + s.y;
    }

    // Softmax over 25
    float mx = logit[0];
#pragma unroll
    for (int kk = 1; kk < 25; kk++) mx = fmaxf(mx, logit[kk]);
    float sum = 0.f;
#pragma unroll
    for (int kk = 0; kk < 25; kk++) { logit[kk] = __expf(logit[kk] - mx); sum += logit[kk]; }
    float inv = __fdividef(1.f, sum);

    // g = attn @ Wg  (Wg rows broadcast from smem)
    ull o[32];
#pragma unroll
    for (int j = 0; j < 32; j++) o[j] = 0ull;
    const ull* wg2 = (const ull*)Wgs;
#pragma unroll
    for (int kk = 0; kk < 25; kk++) {
        float p = logit[kk] * inv;
        ull p2 = pack2(p, p);
        const ull* wrow = wg2 + kk * 32;
#pragma unroll
        for (int j = 0; j < 32; j++)
            o[j] = fma2(p2, wrow[j], o[j]);
    }

    float* op = out + m * 64;
#pragma unroll
    for (int j = 0; j < 16; j++) {
        float2 x = unpack2(o[2 * j]), y = unpack2(o[2 * j + 1]);
        *(float4*)&op[j * 4] = make_float4(x.x, x.y, y.x, y.y);
    }
}

// ---------------- launch ----------------
extern "C" void kernel_launch(void* const* d_in, const int* in_sizes, int n_in,
                              void* d_out, int out_size)
{
    const float* main_in = (const float*)d_in[0];
    const float* ref_in  = (const float*)d_in[1];
    const float* Wm      = (const float*)d_in[2];
    const float* Wr      = (const float*)d_in[3];
    const float* Wg      = (const float*)d_in[4];
    float* out = (float*)d_out;

    conv_kernel<<<dim3(2048, 2), 128>>>(main_in, ref_in, Wm, Wr);

    const int smem_bytes = 32 * CRS_STRIDE * 8 + 1600 * 4;  // 110,080 B
    // Idempotent; attribute persists from the pre-capture correctness call even
    // if a during-capture invocation is a no-op.
    cudaFuncSetAttribute(attn_kernel, cudaFuncAttributeMaxDynamicSharedMemorySize, smem_bytes);

    attn_kernel<<<dim3(16, 16, 4), 256, smem_bytes>>>(Wg, out);
}